// round 1
// baseline (speedup 1.0000x reference)
#include <cuda_runtime.h>
#include <math.h>

// Problem dims
#define NB   32            // batch
#define NT   512           // seq len
#define ND   1024          // input size
#define NH   1024          // hidden size
#define NG   4096          // 4*H
#define MTOT (NB * NT)     // 16384 rows of x_proj

// Scratch (allocation-free rule: __device__ globals)
__device__ float g_xproj[(size_t)MTOT * NG];   // 256 MB
__device__ float g_c[NB * NH];                 // cell state, 128 KB

// ---------------------------------------------------------------------------
// init: zero cell state (must run every replay; graph re-runs from t=0)
// ---------------------------------------------------------------------------
__global__ void init_c_kernel() {
    int i = blockIdx.x * blockDim.x + threadIdx.x;
    if (i < NB * NH) g_c[i] = 0.0f;
}

// ---------------------------------------------------------------------------
// x_proj = x @ W_ih + bias    (M=16384, N=4096, K=1024)
// Classic 128x128x8 tiled SGEMM, 256 threads, 8x8 register tiles.
// ---------------------------------------------------------------------------
__global__ __launch_bounds__(256) void sgemm_xproj(const float* __restrict__ A,
                                                   const float* __restrict__ Bm,
                                                   const float* __restrict__ bias) {
    __shared__ float As[8 * 128];
    __shared__ float Bs[8 * 128];

    const int tid = threadIdx.x;
    const int rowBase = blockIdx.y * 128;
    const int colBase = blockIdx.x * 128;

    const int irA = tid >> 1;          // 0..127
    const int icA = (tid & 1) * 4;     // 0 or 4
    const int irB = tid >> 5;          // 0..7
    const int icB = (tid & 31) * 4;    // 0..124

    const int trow = tid >> 4;         // 0..15
    const int tcol = tid & 15;         // 0..15

    float res[8][8];
#pragma unroll
    for (int i = 0; i < 8; i++)
#pragma unroll
        for (int j = 0; j < 8; j++) res[i][j] = 0.0f;

    for (int bk = 0; bk < ND; bk += 8) {
        float4 a = *(const float4*)&A[(size_t)(rowBase + irA) * ND + bk + icA];
        As[(icA + 0) * 128 + irA] = a.x;
        As[(icA + 1) * 128 + irA] = a.y;
        As[(icA + 2) * 128 + irA] = a.z;
        As[(icA + 3) * 128 + irA] = a.w;
        *(float4*)&Bs[irB * 128 + icB] =
            *(const float4*)&Bm[(size_t)(bk + irB) * NG + colBase + icB];
        __syncthreads();

#pragma unroll
        for (int kk = 0; kk < 8; kk++) {
            float regM[8], regN[8];
            *(float4*)&regM[0] = *(float4*)&As[kk * 128 + trow * 8];
            *(float4*)&regM[4] = *(float4*)&As[kk * 128 + trow * 8 + 4];
            *(float4*)&regN[0] = *(float4*)&Bs[kk * 128 + tcol * 8];
            *(float4*)&regN[4] = *(float4*)&Bs[kk * 128 + tcol * 8 + 4];
#pragma unroll
            for (int i = 0; i < 8; i++)
#pragma unroll
                for (int j = 0; j < 8; j++)
                    res[i][j] += regM[i] * regN[j];
        }
        __syncthreads();
    }

#pragma unroll
    for (int i = 0; i < 8; i++) {
#pragma unroll
        for (int j = 0; j < 8; j += 4) {
            int col = colBase + tcol * 8 + j;
            float4 o;
            o.x = res[i][j + 0] + bias[col + 0];
            o.y = res[i][j + 1] + bias[col + 1];
            o.z = res[i][j + 2] + bias[col + 2];
            o.w = res[i][j + 3] + bias[col + 3];
            *(float4*)&g_xproj[(size_t)(rowBase + trow * 8 + i) * NG + col] = o;
        }
    }
}

// ---------------------------------------------------------------------------
// One LSTM timestep.
// Grid: 128 CTAs, each owns 8 h-columns (base..base+7) => 32 gate columns
//   (i,f,g,o at offsets g*1024 + base + jj).
// 256 threads = 4 warp-pairs; pair p computes the full 32x32 gate tile over
//   K-slice [p*256, p*256+256), K staged in 8 chunks of 128.
// 4x4 register tile per thread (4 batches x 4 gates at fixed column jj=tc).
// Partials reduced via smem, then fused elementwise c/h update.
// h_{t-1} is read directly from the output tensor (hidden_seq).
// ---------------------------------------------------------------------------
__device__ __forceinline__ float sigmoidf_(float x) {
    return 1.0f / (1.0f + __expf(-x));
}

__global__ __launch_bounds__(256) void lstm_step(const float* __restrict__ Whh,
                                                 float* __restrict__ out, int t) {
    // smem: hs [32][129] = 4128 floats, Ws [128][36] = 4608 floats.
    // red [4][1024] = 4096 floats aliases the front (hs dead by then).
    __shared__ float sm[4128 + 4608];
    float* hs = sm;
    float* Ws = sm + 4128;

    const int tid  = threadIdx.x;
    const int base = blockIdx.x * 8;

    const int p  = tid >> 6;        // warp-pair 0..3  (K slice)
    const int lt = tid & 63;
    const int tr = lt >> 3;         // 0..7 -> batches 4*tr..4*tr+3
    const int tc = lt & 7;          // 0..7 -> column jj

    float acc[4][4];
#pragma unroll
    for (int i = 0; i < 4; i++)
#pragma unroll
        for (int j = 0; j < 4; j++) acc[i][j] = 0.0f;

    if (t > 0) {
        const size_t hrow_stride = (size_t)NT * NH;   // stride between batches
        const size_t hoff = (size_t)(t - 1) * NH;     // offset of h_{t-1} row

        for (int cch = 0; cch < 8; cch++) {
            const int kb = cch * 128;

            // stage h chunk: hs[b][k] (pad 129)
#pragma unroll
            for (int i = 0; i < 4; i++) {
                int lin = tid + i * 256;        // 0..1023
                int b   = lin >> 5;
                int kq  = lin & 31;
                float4 v = *(const float4*)&out[(size_t)b * hrow_stride + hoff + kb + kq * 4];
                float* d = &hs[b * 129 + kq * 4];
                d[0] = v.x; d[1] = v.y; d[2] = v.z; d[3] = v.w;
            }
            // stage W chunk: Ws[k][g*8+jj] (pad 36)
#pragma unroll
            for (int i = 0; i < 4; i++) {
                int lin = tid + i * 256;        // 0..1023
                int kl  = lin >> 3;             // 0..127
                int rem = lin & 7;
                int g   = rem >> 1;
                int q   = rem & 1;
                *(float4*)&Ws[kl * 36 + g * 8 + q * 4] =
                    *(const float4*)&Whh[(size_t)(kb + kl) * NG + g * 1024 + base + q * 4];
            }
            __syncthreads();

#pragma unroll
            for (int kk = 0; kk < 32; kk++) {
                const int k = (p << 5) + kk;
                const float h0 = hs[(tr * 4 + 0) * 129 + k];
                const float h1 = hs[(tr * 4 + 1) * 129 + k];
                const float h2 = hs[(tr * 4 + 2) * 129 + k];
                const float h3 = hs[(tr * 4 + 3) * 129 + k];
                const float* wr = &Ws[k * 36 + tc];
                const float w0 = wr[0];
                const float w1 = wr[8];
                const float w2 = wr[16];
                const float w3 = wr[24];
                acc[0][0] += h0 * w0; acc[0][1] += h0 * w1; acc[0][2] += h0 * w2; acc[0][3] += h0 * w3;
                acc[1][0] += h1 * w0; acc[1][1] += h1 * w1; acc[1][2] += h1 * w2; acc[1][3] += h1 * w3;
                acc[2][0] += h2 * w0; acc[2][1] += h2 * w1; acc[2][2] += h2 * w2; acc[2][3] += h2 * w3;
                acc[3][0] += h3 * w0; acc[3][1] += h3 * w1; acc[3][2] += h3 * w2; acc[3][3] += h3 * w3;
            }
            __syncthreads();
        }
    }

    // reduce the 4 K-partials through smem
    float* red = sm;   // [4][1024]; hs/Ws are dead (sync above guarantees)
#pragma unroll
    for (int bi = 0; bi < 4; bi++)
#pragma unroll
        for (int g = 0; g < 4; g++)
            red[p * 1024 + (tr * 4 + bi) * 32 + g * 8 + tc] = acc[bi][g];
    __syncthreads();

    // fused gate nonlinearity + c/h update; thread owns (b, jj)
    const int b  = tid >> 3;     // 0..31
    const int jj = tid & 7;      // 0..7
    float gate[4];
#pragma unroll
    for (int g = 0; g < 4; g++) {
        int col = b * 32 + g * 8 + jj;
        float s = red[col] + red[1024 + col] + red[2048 + col] + red[3072 + col];
        s += g_xproj[((size_t)b * NT + t) * NG + g * 1024 + base + jj];
        gate[g] = s;
    }
    const float ig = sigmoidf_(gate[0]);
    const float fg = sigmoidf_(gate[1]);
    const float gg = tanhf(gate[2]);
    const float og = sigmoidf_(gate[3]);

    const int ci = b * NH + base + jj;
    const float c = fg * g_c[ci] + ig * gg;
    g_c[ci] = c;
    out[((size_t)b * NT + t) * NH + base + jj] = og * tanhf(c);
}

// ---------------------------------------------------------------------------
// finalize: append h_T and c_T after hidden_seq (flattened pytree order:
// hidden_seq, h_T, c_T)
// ---------------------------------------------------------------------------
__global__ void finalize_kernel(float* __restrict__ out) {
    int i = blockIdx.x * blockDim.x + threadIdx.x;
    if (i < NB * NH) {
        const size_t HS = (size_t)NB * NT * NH;   // 16777216
        int b = i >> 10;
        int k = i & 1023;
        out[HS + i] = out[((size_t)b * NT + (NT - 1)) * NH + k];
        out[HS + NB * NH + i] = g_c[i];
    }
}

// ---------------------------------------------------------------------------
// launch
// ---------------------------------------------------------------------------
extern "C" void kernel_launch(void* const* d_in, const int* in_sizes, int n_in,
                              void* d_out, int out_size) {
    const float* x    = (const float*)d_in[0];
    const float* wih  = (const float*)d_in[1];
    const float* whh  = (const float*)d_in[2];
    const float* bias = (const float*)d_in[3];
    float* out = (float*)d_out;

    (void)in_sizes; (void)n_in;

    // zero cell state (graph replays restart from t=0)
    init_c_kernel<<<(NB * NH + 255) / 256, 256>>>();

    // x_proj = x @ W_ih + bias
    {
        dim3 grid(NG / 128, MTOT / 128);   // (32, 128)
        sgemm_xproj<<<grid, 256>>>(x, wih, bias);
    }

    // recurrence: 512 dependent step kernels
    for (int t = 0; t < NT; t++) {
        lstm_step<<<NH / 8, 256>>>(whh, out, t);
    }

    // append (h_T, c_T) if the output buffer includes them
    if (out_size >= NB * NT * NH + 2 * NB * NH) {
        finalize_kernel<<<(NB * NH + 255) / 256, 256>>>(out);
    }
}